// round 1
// baseline (speedup 1.0000x reference)
#include <cuda_runtime.h>
#include <math.h>

// ---------------- problem constants ----------------
#define Bc 4
#define Tc 8
#define Cc 256
#define Nc 196
#define Hc 4
#define Sc (Tc * Nc)          // 1568
#define BHc (Bc * Hc)         // 16
#define EPSc 1e-5f

// ---------------- scratch (device globals; no allocations allowed) ----------
__device__ float g_X[Bc * Sc * Cc];            // transposed emb  [B,S,C]
__device__ float g_Q[BHc * Sc * Cc];           // [B,H,S,C]
__device__ float g_K[BHc * Sc * Cc];
__device__ float g_V[BHc * Sc * Cc];
__device__ float g_S[(size_t)BHc * Sc * Sc];   // scores / probs (157 MB)
__device__ float g_CTXH[BHc * Sc * Cc];        // per-head ctx
__device__ float g_CTX[Bc * Sc * Cc];          // head-mean ctx

#define CHUNK 4096
#define NCHUNK ((Sc * Sc + CHUNK - 1) / CHUNK) // 601
__device__ float g_part[BHc * NCHUNK * 2];
__device__ float g_mean[BHc];
__device__ float g_rstd[BHc];

// ---------------- transpose: emb (B,T,C,N) -> g_X (B, T*N, C) --------------
__global__ void k_transpose(const float* __restrict__ emb) {
    __shared__ float tile[32][33];
    int bt = blockIdx.z;                 // b*T + t
    int n0 = blockIdx.x * 32;
    int c0 = blockIdx.y * 32;
    int x = threadIdx.x, y = threadIdx.y;   // 32 x 8
    const float* src = emb + (size_t)bt * Cc * Nc;
    float* dst = g_X + (size_t)bt * Nc * Cc;
#pragma unroll
    for (int i = 0; i < 32; i += 8) {
        int c = c0 + y + i, n = n0 + x;
        tile[y + i][x] = (n < Nc && c < Cc) ? src[c * Nc + n] : 0.f;
    }
    __syncthreads();
#pragma unroll
    for (int i = 0; i < 32; i += 8) {
        int n = n0 + y + i, c = c0 + x;
        if (n < Nc && c < Cc) dst[n * Cc + c] = tile[x][y + i];
    }
}

// ---------------- generic 64x64x16 tiled SGEMM tile body --------------------
// NT=true : Out[m,n] = alpha * sum_k A[m,k] * Bm[n,k]   (Bm row-major [n][k])
// NT=false: Out[m,n] = alpha * sum_k A[m,k] * Bm[k,n]   (Bm row-major [k][n])
#define BM 64
#define BN 64
#define BK 16

template <bool NT>
__device__ __forceinline__ void gemm_tile(const float* __restrict__ A,
                                          const float* __restrict__ Bm,
                                          float* __restrict__ Co,
                                          int M, int Nn, int K,
                                          int lda, int ldb, int ldc,
                                          float alpha) {
    __shared__ float As[BK][BM];
    __shared__ float Bs[BK][BN];

    const int tx = threadIdx.x;            // 0..15
    const int ty = threadIdx.y;            // 0..15
    const int tid = ty * 16 + tx;
    const int m0 = blockIdx.x * BM;
    const int n0 = blockIdx.y * BN;

    float acc[4][4];
#pragma unroll
    for (int i = 0; i < 4; i++)
#pragma unroll
        for (int j = 0; j < 4; j++) acc[i][j] = 0.f;

    for (int k0 = 0; k0 < K; k0 += BK) {
        // load A tile: 64 rows x 16 k (K is always a multiple of 16 here)
#pragma unroll
        for (int l = 0; l < 4; l++) {
            int idx = tid + l * 256;
            int r = idx >> 4, c = idx & 15;
            int gm = m0 + r;
            As[c][r] = (gm < M) ? A[(size_t)gm * lda + k0 + c] : 0.f;
        }
        // load B tile
        if (NT) {
#pragma unroll
            for (int l = 0; l < 4; l++) {
                int idx = tid + l * 256;
                int n = idx >> 4, c = idx & 15;
                int gn = n0 + n;
                Bs[c][n] = (gn < Nn) ? Bm[(size_t)gn * ldb + k0 + c] : 0.f;
            }
        } else {
#pragma unroll
            for (int l = 0; l < 4; l++) {
                int idx = tid + l * 256;
                int k = idx >> 6, n = idx & 63;
                int gn = n0 + n;
                Bs[k][n] = (gn < Nn) ? Bm[(size_t)(k0 + k) * ldb + gn] : 0.f;
            }
        }
        __syncthreads();
#pragma unroll
        for (int k = 0; k < BK; k++) {
            float4 a = *(const float4*)&As[k][ty * 4];
            float4 b = *(const float4*)&Bs[k][tx * 4];
            float av[4] = {a.x, a.y, a.z, a.w};
            float bv[4] = {b.x, b.y, b.z, b.w};
#pragma unroll
            for (int i = 0; i < 4; i++)
#pragma unroll
                for (int j = 0; j < 4; j++) acc[i][j] += av[i] * bv[j];
        }
        __syncthreads();
    }
#pragma unroll
    for (int i = 0; i < 4; i++) {
        int gm = m0 + ty * 4 + i;
        if (gm >= M) continue;
#pragma unroll
        for (int j = 0; j < 4; j++) {
            int gn = n0 + tx * 4 + j;
            if (gn < Nn) Co[(size_t)gm * ldc + gn] = alpha * acc[i][j];
        }
    }
}

// ---------------- GEMM driver kernels ---------------------------------------
__global__ __launch_bounds__(256) void k_qkv(const float* __restrict__ Wq,
                                             const float* __restrict__ Wk,
                                             const float* __restrict__ Wv) {
    int z = blockIdx.z;
    int which = z / BHc;        // 0=Q 1=K 2=V
    int bh = z % BHc;
    int b = bh / Hc, h = bh % Hc;
    const float* A = g_X + (size_t)b * Sc * Cc;
    const float* W = (which == 0 ? Wq : which == 1 ? Wk : Wv) + (size_t)h * Cc * Cc;
    float* out = (which == 0 ? g_Q : which == 1 ? g_K : g_V) + (size_t)bh * Sc * Cc;
    gemm_tile<true>(A, W, out, Sc, Cc, Cc, Cc, Cc, Cc, 1.0f);
}

__global__ __launch_bounds__(256) void k_scores(float scale) {
    int bh = blockIdx.z;
    const float* Aq = g_Q + (size_t)bh * Sc * Cc;
    const float* Bk = g_K + (size_t)bh * Sc * Cc;
    float* out = g_S + (size_t)bh * Sc * Sc;
    gemm_tile<true>(Aq, Bk, out, Sc, Sc, Cc, Cc, Cc, Sc, scale);
}

__global__ __launch_bounds__(256) void k_ctx() {
    int bh = blockIdx.z;
    const float* Ap = g_S + (size_t)bh * Sc * Sc;
    const float* Bv = g_V + (size_t)bh * Sc * Cc;
    float* out = g_CTXH + (size_t)bh * Sc * Cc;
    gemm_tile<false>(Ap, Bv, out, Sc, Cc, Sc, Sc, Cc, Cc, 1.0f);
}

__global__ __launch_bounds__(256) void k_oproj(const float* __restrict__ Wo,
                                               float* __restrict__ out) {
    gemm_tile<true>(g_CTX, Wo, out, Bc * Sc, Cc, Cc, Cc, Cc, Cc, 1.0f);
}

// ---------------- instance-norm stats (two-stage, deterministic) ------------
__global__ __launch_bounds__(256) void k_stats1() {
    int bh = blockIdx.y;
    int ch = blockIdx.x;
    size_t base = (size_t)bh * Sc * Sc;
    int start = ch * CHUNK;
    float s = 0.f, q = 0.f;
    for (int i = threadIdx.x; i < CHUNK; i += 256) {
        int idx = start + i;
        if (idx < Sc * Sc) {
            float v = g_S[base + idx];
            s += v;
            q += v * v;
        }
    }
    __shared__ float ss[256], sq[256];
    int tid = threadIdx.x;
    ss[tid] = s; sq[tid] = q;
    __syncthreads();
    for (int st = 128; st > 0; st >>= 1) {
        if (tid < st) { ss[tid] += ss[tid + st]; sq[tid] += sq[tid + st]; }
        __syncthreads();
    }
    if (tid == 0) {
        g_part[((size_t)bh * NCHUNK + ch) * 2 + 0] = ss[0];
        g_part[((size_t)bh * NCHUNK + ch) * 2 + 1] = sq[0];
    }
}

__global__ __launch_bounds__(256) void k_stats2() {
    int bh = blockIdx.x;
    float s = 0.f, q = 0.f;
    for (int i = threadIdx.x; i < NCHUNK; i += 256) {
        s += g_part[((size_t)bh * NCHUNK + i) * 2 + 0];
        q += g_part[((size_t)bh * NCHUNK + i) * 2 + 1];
    }
    __shared__ float ss[256], sq[256];
    int tid = threadIdx.x;
    ss[tid] = s; sq[tid] = q;
    __syncthreads();
    for (int st = 128; st > 0; st >>= 1) {
        if (tid < st) { ss[tid] += ss[tid + st]; sq[tid] += sq[tid + st]; }
        __syncthreads();
    }
    if (tid == 0) {
        float cnt = (float)Sc * (float)Sc;
        float mean = ss[0] / cnt;
        float var = sq[0] / cnt - mean * mean;
        g_mean[bh] = mean;
        g_rstd[bh] = rsqrtf(var + EPSc);
    }
}

// ---------------- fused instance-norm apply + softmax (row-wise) ------------
__global__ __launch_bounds__(256) void k_softmax() {
    int row = blockIdx.x;             // 0 .. B*H*S-1, row index into [bh][s][*]
    int bh = row / Sc;
    size_t base = (size_t)row * Sc;
    __shared__ float buf[Sc];
    __shared__ float red[256];
    int tid = threadIdx.x;
    float mean = g_mean[bh], rstd = g_rstd[bh];

    float lmax = -3.4e38f;
    for (int i = tid; i < Sc; i += 256) {
        float v = (g_S[base + i] - mean) * rstd;
        buf[i] = v;
        lmax = fmaxf(lmax, v);
    }
    red[tid] = lmax;
    __syncthreads();
    for (int st = 128; st > 0; st >>= 1) {
        if (tid < st) red[tid] = fmaxf(red[tid], red[tid + st]);
        __syncthreads();
    }
    float rmax = red[0];
    __syncthreads();

    float lsum = 0.f;
    for (int i = tid; i < Sc; i += 256) {
        float e = __expf(buf[i] - rmax);
        buf[i] = e;
        lsum += e;
    }
    red[tid] = lsum;
    __syncthreads();
    for (int st = 128; st > 0; st >>= 1) {
        if (tid < st) red[tid] += red[tid + st];
        __syncthreads();
    }
    float inv = 1.f / red[0];
    __syncthreads();

    for (int i = tid; i < Sc; i += 256) g_S[base + i] = buf[i] * inv;
}

// ---------------- head mean -------------------------------------------------
__global__ __launch_bounds__(256) void k_hmean() {
    int idx = blockIdx.x * 256 + threadIdx.x;   // over B*S*C
    if (idx >= Bc * Sc * Cc) return;
    int b = idx / (Sc * Cc);
    int rem = idx % (Sc * Cc);
    float s = 0.f;
#pragma unroll
    for (int h = 0; h < Hc; h++)
        s += g_CTXH[((size_t)(b * Hc + h) * Sc * Cc) + rem];
    g_CTX[idx] = 0.25f * s;
}

// ---------------- launch ----------------------------------------------------
extern "C" void kernel_launch(void* const* d_in, const int* in_sizes, int n_in,
                              void* d_out, int out_size) {
    const float* emb = (const float*)d_in[0];
    const float* Wq  = (const float*)d_in[1];
    const float* Wk  = (const float*)d_in[2];
    const float* Wv  = (const float*)d_in[3];
    const float* Wo  = (const float*)d_in[4];
    float* out = (float*)d_out;

    const float scale = 1.0f / sqrtf((float)Sc);

    // 1) transpose emb -> x [B,S,C]
    k_transpose<<<dim3(7, 8, Bc * Tc), dim3(32, 8)>>>(emb);

    // 2) QKV projections: M=1568 (25 tiles), N=256 (4 tiles), z = 3*B*H
    k_qkv<<<dim3(25, 4, 3 * BHc), dim3(16, 16)>>>(Wq, Wk, Wv);

    // 3) scores = (Q K^T)/sqrt(S): M=N=1568 (25x25), z = B*H
    k_scores<<<dim3(25, 25, BHc), dim3(16, 16)>>>(scale);

    // 4) instance-norm stats (deterministic two-stage)
    k_stats1<<<dim3(NCHUNK, BHc), 256>>>();
    k_stats2<<<BHc, 256>>>();

    // 5) norm + softmax (in place on g_S)
    k_softmax<<<BHc * Sc, 256>>>();

    // 6) ctx = probs @ V
    k_ctx<<<dim3(25, 4, BHc), dim3(16, 16)>>>();

    // 7) mean over heads
    k_hmean<<<(Bc * Sc * Cc + 255) / 256, 256>>>();

    // 8) output projection straight into d_out (flat layout matches reshape)
    k_oproj<<<dim3(98, 4, 1), dim3(16, 16)>>>(Wo, out);
}

// round 3
// speedup vs baseline: 2.8818x; 2.8818x over previous
#include <cuda_runtime.h>
#include <cuda_bf16.h>
#include <cstdint>
#include <math.h>

// ---------------- problem constants ----------------
#define Bc 4
#define Tc 8
#define Cc 256
#define Nc 196
#define Hc 4
#define Sc (Tc * Nc)          // 1568
#define BHc (Bc * Hc)         // 16
#define MSc (Bc * Sc)         // 6272
#define EPSc 1e-5f
#define NTILE (13 * 13)       // score tiles per bh

typedef __nv_bfloat16 bf16;

// ---------------- scratch (device globals) ----------------------------------
__device__ bf16  g_Xhi[Bc * Sc * Cc],  g_Xlo[Bc * Sc * Cc];
__device__ bf16  g_Wqhi[Hc * Cc * Cc], g_Wqlo[Hc * Cc * Cc];
__device__ bf16  g_Wkhi[Hc * Cc * Cc], g_Wklo[Hc * Cc * Cc];
__device__ bf16  g_Wvhi[Hc * Cc * Cc], g_Wvlo[Hc * Cc * Cc];
__device__ bf16  g_Wohi[Cc * Cc],      g_Wolo[Cc * Cc];
__device__ bf16  gQhi[BHc * Sc * Cc],  gQlo[BHc * Sc * Cc];
__device__ bf16  gKhi[BHc * Sc * Cc],  gKlo[BHc * Sc * Cc];
__device__ float g_Vf32[BHc * Sc * Cc];
__device__ bf16  gVThi[BHc * Cc * Sc], gVTlo[BHc * Cc * Sc];
__device__ float g_S[(size_t)BHc * Sc * Sc];            // fp32 scores
__device__ bf16  gPhi[(size_t)BHc * Sc * Sc], gPlo[(size_t)BHc * Sc * Sc];
__device__ float g_CTXH[BHc * Sc * Cc];
__device__ bf16  gCThi[Bc * Sc * Cc],  gCTlo[Bc * Sc * Cc];
__device__ float g_part[BHc * NTILE * 2];
__device__ float g_mean[BHc], g_rstd[BHc];

// ---------------- PTX helpers ------------------------------------------------
__device__ __forceinline__ uint32_t cvta_smem(const void* p) {
    uint32_t a;
    asm("{ .reg .u64 t; cvta.to.shared.u64 t, %1; cvt.u32.u64 %0, t; }" : "=r"(a) : "l"(p));
    return a;
}

__device__ __forceinline__ void ldsm_x4(uint32_t& r0, uint32_t& r1, uint32_t& r2,
                                        uint32_t& r3, uint32_t addr) {
    asm volatile("ldmatrix.sync.aligned.m8n8.x4.shared.b16 {%0,%1,%2,%3}, [%4];"
                 : "=r"(r0), "=r"(r1), "=r"(r2), "=r"(r3) : "r"(addr));
}

__device__ __forceinline__ void mma16816(float* d, const uint32_t* a, const uint32_t* b) {
    asm volatile("mma.sync.aligned.m16n8k16.row.col.f32.bf16.bf16.f32 "
                 "{%0,%1,%2,%3}, {%4,%5,%6,%7}, {%8,%9}, {%0,%1,%2,%3};"
                 : "+f"(d[0]), "+f"(d[1]), "+f"(d[2]), "+f"(d[3])
                 : "r"(a[0]), "r"(a[1]), "r"(a[2]), "r"(a[3]), "r"(b[0]), "r"(b[1]));
}

// ---------------- generic 128x128 bf16-split HMMA GEMM -----------------------
// NT form: C[m,n] = alpha * sum_k A[m,k]*B[n,k]; A,B row-major (k contiguous)
#define EPI_F32    0
#define EPI_SCORES 1
#define EPI_SPLIT  2

// smem: 4 operand tiles (Ahi,Alo,Bhi,Blo), each 128 rows x 48B (16 bf16 + pad)
#define TILE_BYTES 6144

static __device__ __forceinline__ void gemm_body(
        const bf16* __restrict__ Ahi, const bf16* __restrict__ Alo,
        const bf16* __restrict__ Bhi, const bf16* __restrict__ Blo,
        int M, int N, int K, int lda, int ldb,
        int m0, int n0, int epi, float alpha,
        float* Cf, bf16* Chi, bf16* Clo, int ldc, float* part) {
    __shared__ uint4 smem4[4 * TILE_BYTES / 16];
    __shared__ float red[8];
    char* smem = (char*)smem4;
    const int tid = threadIdx.x;            // 128 threads, 4 warps
    const int wid = tid >> 5, lane = tid & 31;
    const int wm = (wid >> 1) * 64, wn = (wid & 1) * 64;
    const uint32_t sb = cvta_smem(smem);

    float acc[4][8][4];
#pragma unroll
    for (int i = 0; i < 4; i++)
#pragma unroll
        for (int j = 0; j < 8; j++)
#pragma unroll
            for (int e = 0; e < 4; e++) acc[i][j][e] = 0.f;

    const uint4 z4 = make_uint4(0u, 0u, 0u, 0u);
    const int nch = K >> 4;                 // K is always a multiple of 16
    for (int ch = 0; ch < nch; ch++) {
        const int k0 = ch << 4;
        // global -> smem: 4 arrays x 128 rows x 2 16B-units = 1024 uint4
        __syncthreads();
#pragma unroll
        for (int l = 0; l < 8; l++) {
            int it = tid + l * 128;
            int arr = it >> 8;
            int rem = it & 255;
            int r = rem >> 1, u = rem & 1;
            const bf16* src;
            bool valid;
            if (arr < 2) {
                valid = (m0 + r) < M;
                src = (arr == 0 ? Ahi : Alo) + (size_t)(m0 + r) * lda + k0 + u * 8;
            } else {
                valid = (n0 + r) < N;
                src = (arr == 2 ? Bhi : Blo) + (size_t)(n0 + r) * ldb + k0 + u * 8;
            }
            *(uint4*)(smem + arr * TILE_BYTES + r * 48 + u * 16) =
                valid ? *(const uint4*)src : z4;
        }
        __syncthreads();

        // fragment loads via ldmatrix (conflict-free with 48B row stride)
        uint32_t af[2][4][4];   // [hi/lo][im][reg]
        uint32_t bfr[2][8][2];  // [hi/lo][n8 tile][reg]
        const uint32_t lrow = (uint32_t)(lane & 15);
        const uint32_t lu = (uint32_t)(lane >> 4);
#pragma unroll
        for (int hl = 0; hl < 2; hl++) {
#pragma unroll
            for (int im = 0; im < 4; im++) {
                uint32_t addr = sb + hl * TILE_BYTES +
                                (wm + im * 16 + lrow) * 48 + lu * 16;
                ldsm_x4(af[hl][im][0], af[hl][im][1], af[hl][im][2], af[hl][im][3], addr);
            }
#pragma unroll
            for (int inn = 0; inn < 4; inn++) {
                uint32_t addr = sb + (2 + hl) * TILE_BYTES +
                                (wn + inn * 16 + lrow) * 48 + lu * 16;
                uint32_t r0, r1, r2, r3;
                ldsm_x4(r0, r1, r2, r3, addr);
                bfr[hl][inn * 2 + 0][0] = r0; bfr[hl][inn * 2 + 0][1] = r2;
                bfr[hl][inn * 2 + 1][0] = r1; bfr[hl][inn * 2 + 1][1] = r3;
            }
        }
        // 3-term split MMAs
#pragma unroll
        for (int im = 0; im < 4; im++)
#pragma unroll
            for (int jn = 0; jn < 8; jn++) {
                mma16816(acc[im][jn], af[0][im], bfr[0][jn]);  // hi*hi
                mma16816(acc[im][jn], af[0][im], bfr[1][jn]);  // hi*lo
                mma16816(acc[im][jn], af[1][im], bfr[0][jn]);  // lo*hi
            }
    }

    // ---------------- epilogue ----------------
    float psum = 0.f, psq = 0.f;
#pragma unroll
    for (int im = 0; im < 4; im++) {
#pragma unroll
        for (int jn = 0; jn < 8; jn++) {
            int r0 = m0 + wm + im * 16 + (lane >> 2);
            int cn = n0 + wn + jn * 8 + (lane & 3) * 2;
            bool cv = cn < N;   // pair (cn, cn+1): valid-N region is even
            float v0 = acc[im][jn][0] * alpha, v1 = acc[im][jn][1] * alpha;
            float v2 = acc[im][jn][2] * alpha, v3 = acc[im][jn][3] * alpha;
            if (epi == EPI_SPLIT) {
                if (cv && r0 < M) {
                    bf16 h0 = __float2bfloat16(v0), h1 = __float2bfloat16(v1);
                    __nv_bfloat162 hh; hh.x = h0; hh.y = h1;
                    __nv_bfloat162 ll;
                    ll.x = __float2bfloat16(v0 - __bfloat162float(h0));
                    ll.y = __float2bfloat16(v1 - __bfloat162float(h1));
                    *(__nv_bfloat162*)&Chi[(size_t)r0 * ldc + cn] = hh;
                    *(__nv_bfloat162*)&Clo[(size_t)r0 * ldc + cn] = ll;
                }
                if (cv && r0 + 8 < M) {
                    bf16 h2 = __float2bfloat16(v2), h3 = __float2bfloat16(v3);
                    __nv_bfloat162 hh; hh.x = h2; hh.y = h3;
                    __nv_bfloat162 ll;
                    ll.x = __float2bfloat16(v2 - __bfloat162float(h2));
                    ll.y = __float2bfloat16(v3 - __bfloat162float(h3));
                    *(__nv_bfloat162*)&Chi[(size_t)(r0 + 8) * ldc + cn] = hh;
                    *(__nv_bfloat162*)&Clo[(size_t)(r0 + 8) * ldc + cn] = ll;
                }
            } else {
                if (cv && r0 < M) {
                    *(float2*)&Cf[(size_t)r0 * ldc + cn] = make_float2(v0, v1);
                    psum += v0 + v1; psq += v0 * v0 + v1 * v1;
                }
                if (cv && r0 + 8 < M) {
                    *(float2*)&Cf[(size_t)(r0 + 8) * ldc + cn] = make_float2(v2, v3);
                    psum += v2 + v3; psq += v2 * v2 + v3 * v3;
                }
            }
        }
    }
    if (epi == EPI_SCORES) {
#pragma unroll
        for (int o = 16; o; o >>= 1) {
            psum += __shfl_xor_sync(0xffffffffu, psum, o);
            psq  += __shfl_xor_sync(0xffffffffu, psq,  o);
        }
        if (lane == 0) { red[wid] = psum; red[4 + wid] = psq; }
        __syncthreads();
        if (tid == 0) {
            part[0] = red[0] + red[1] + red[2] + red[3];
            part[1] = red[4] + red[5] + red[6] + red[7];
        }
    }
}

// ---------------- GEMM wrappers ----------------------------------------------
__global__ __launch_bounds__(128) void k_gemm_qkv() {
    int z = blockIdx.z;
    int bh = z / 3, which = z % 3;
    int b = bh / Hc, h = bh % Hc;
    const bf16* Ah = g_Xhi + (size_t)b * Sc * Cc;
    const bf16* Al = g_Xlo + (size_t)b * Sc * Cc;
    const bf16 *Bh, *Bl;
    if (which == 0)      { Bh = g_Wqhi + (size_t)h * Cc * Cc; Bl = g_Wqlo + (size_t)h * Cc * Cc; }
    else if (which == 1) { Bh = g_Wkhi + (size_t)h * Cc * Cc; Bl = g_Wklo + (size_t)h * Cc * Cc; }
    else                 { Bh = g_Wvhi + (size_t)h * Cc * Cc; Bl = g_Wvlo + (size_t)h * Cc * Cc; }
    int m0 = blockIdx.x * 128, n0 = blockIdx.y * 128;
    if (which == 2) {
        gemm_body(Ah, Al, Bh, Bl, Sc, Cc, Cc, Cc, Cc, m0, n0, EPI_F32, 1.f,
                  g_Vf32 + (size_t)bh * Sc * Cc, nullptr, nullptr, Cc, nullptr);
    } else {
        bf16* Chi = (which == 0 ? gQhi : gKhi) + (size_t)bh * Sc * Cc;
        bf16* Clo = (which == 0 ? gQlo : gKlo) + (size_t)bh * Sc * Cc;
        gemm_body(Ah, Al, Bh, Bl, Sc, Cc, Cc, Cc, Cc, m0, n0, EPI_SPLIT, 1.f,
                  nullptr, Chi, Clo, Cc, nullptr);
    }
}

__global__ __launch_bounds__(128) void k_gemm_sc() {
    int bh = blockIdx.z;
    int m0 = blockIdx.x * 128, n0 = blockIdx.y * 128;
    float alpha = rsqrtf((float)Sc);
    gemm_body(gQhi + (size_t)bh * Sc * Cc, gQlo + (size_t)bh * Sc * Cc,
              gKhi + (size_t)bh * Sc * Cc, gKlo + (size_t)bh * Sc * Cc,
              Sc, Sc, Cc, Cc, Cc, m0, n0, EPI_SCORES, alpha,
              g_S + (size_t)bh * Sc * Sc, nullptr, nullptr, Sc,
              &g_part[((size_t)bh * NTILE + blockIdx.y * 13 + blockIdx.x) * 2]);
}

__global__ __launch_bounds__(128) void k_gemm_ctx() {
    int bh = blockIdx.z;
    int m0 = blockIdx.x * 128, n0 = blockIdx.y * 128;
    gemm_body(gPhi + (size_t)bh * Sc * Sc, gPlo + (size_t)bh * Sc * Sc,
              gVThi + (size_t)bh * Cc * Sc, gVTlo + (size_t)bh * Cc * Sc,
              Sc, Cc, Sc, Sc, Sc, m0, n0, EPI_F32, 1.f,
              g_CTXH + (size_t)bh * Sc * Cc, nullptr, nullptr, Cc, nullptr);
}

__global__ __launch_bounds__(128) void k_gemm_o(float* __restrict__ out) {
    int m0 = blockIdx.x * 128, n0 = blockIdx.y * 128;
    gemm_body(gCThi, gCTlo, g_Wohi, g_Wolo,
              MSc, Cc, Cc, Cc, Cc, m0, n0, EPI_F32, 1.f,
              out, nullptr, nullptr, Cc, nullptr);
}

// ---------------- elementwise / reshape kernels -------------------------------
__global__ void k_transpose(const float* __restrict__ emb) {
    __shared__ float tile[32][33];
    int bt = blockIdx.z;
    int n0 = blockIdx.x * 32, c0 = blockIdx.y * 32;
    int x = threadIdx.x, y = threadIdx.y;
    const float* src = emb + (size_t)bt * Cc * Nc;
    bf16* dh = g_Xhi + (size_t)bt * Nc * Cc;
    bf16* dl = g_Xlo + (size_t)bt * Nc * Cc;
#pragma unroll
    for (int i = 0; i < 32; i += 8) {
        int c = c0 + y + i, n = n0 + x;
        tile[y + i][x] = (n < Nc) ? src[c * Nc + n] : 0.f;
    }
    __syncthreads();
#pragma unroll
    for (int i = 0; i < 32; i += 8) {
        int n = n0 + y + i, c = c0 + x;
        if (n < Nc) {
            float v = tile[x][y + i];
            bf16 h = __float2bfloat16(v);
            dh[n * Cc + c] = h;
            dl[n * Cc + c] = __float2bfloat16(v - __bfloat162float(h));
        }
    }
}

__global__ void k_cvt(const float* __restrict__ s, bf16* __restrict__ h,
                      bf16* __restrict__ l, int n) {
    int i = blockIdx.x * 256 + threadIdx.x;
    if (i < n) {
        float v = s[i];
        bf16 x = __float2bfloat16(v);
        h[i] = x;
        l[i] = __float2bfloat16(v - __bfloat162float(x));
    }
}

// V [bh][S][C] fp32 -> VT [bh][C][S] bf16 hi/lo
__global__ void k_vtrans() {
    __shared__ float t[32][33];
    int bh = blockIdx.z;
    int s0 = blockIdx.x * 32, c0 = blockIdx.y * 32;
    int x = threadIdx.x, y = threadIdx.y;
    const float* V = g_Vf32 + (size_t)bh * Sc * Cc;
    bf16* th = gVThi + (size_t)bh * Cc * Sc;
    bf16* tl = gVTlo + (size_t)bh * Cc * Sc;
#pragma unroll
    for (int i = 0; i < 32; i += 8)
        t[y + i][x] = V[(size_t)(s0 + y + i) * Cc + c0 + x];
    __syncthreads();
#pragma unroll
    for (int i = 0; i < 32; i += 8) {
        float v = t[x][y + i];
        bf16 h = __float2bfloat16(v);
        th[(size_t)(c0 + y + i) * Sc + s0 + x] = h;
        tl[(size_t)(c0 + y + i) * Sc + s0 + x] = __float2bfloat16(v - __bfloat162float(h));
    }
}

__global__ __launch_bounds__(256) void k_stats2() {
    int bh = blockIdx.x;
    float s = 0.f, q = 0.f;
    for (int i = threadIdx.x; i < NTILE; i += 256) {
        s += g_part[((size_t)bh * NTILE + i) * 2 + 0];
        q += g_part[((size_t)bh * NTILE + i) * 2 + 1];
    }
    __shared__ float ss[256], sq[256];
    int tid = threadIdx.x;
    ss[tid] = s; sq[tid] = q;
    __syncthreads();
    for (int st = 128; st > 0; st >>= 1) {
        if (tid < st) { ss[tid] += ss[tid + st]; sq[tid] += sq[tid + st]; }
        __syncthreads();
    }
    if (tid == 0) {
        float cnt = (float)Sc * (float)Sc;
        float mean = ss[0] / cnt;
        float var = sq[0] / cnt - mean * mean;
        g_mean[bh] = mean;
        g_rstd[bh] = rsqrtf(var + EPSc);
    }
}

__global__ __launch_bounds__(256) void k_softmax() {
    int row = blockIdx.x;
    int bh = row / Sc;
    size_t base = (size_t)row * Sc;
    __shared__ float buf[Sc];
    __shared__ float red[256];
    int tid = threadIdx.x;
    float mean = g_mean[bh], rstd = g_rstd[bh];

    float lmax = -3.4e38f;
    for (int i = tid; i < Sc; i += 256) {
        float v = (g_S[base + i] - mean) * rstd;
        buf[i] = v;
        lmax = fmaxf(lmax, v);
    }
    red[tid] = lmax;
    __syncthreads();
    for (int st = 128; st > 0; st >>= 1) {
        if (tid < st) red[tid] = fmaxf(red[tid], red[tid + st]);
        __syncthreads();
    }
    float rmax = red[0];
    __syncthreads();

    float lsum = 0.f;
    for (int i = tid; i < Sc; i += 256) {
        float e = __expf(buf[i] - rmax);
        buf[i] = e;
        lsum += e;
    }
    red[tid] = lsum;
    __syncthreads();
    for (int st = 128; st > 0; st >>= 1) {
        if (tid < st) red[tid] += red[tid + st];
        __syncthreads();
    }
    float inv = 1.f / red[0];
    __syncthreads();

    for (int i = tid; i < Sc; i += 256) {
        float p = buf[i] * inv;
        bf16 h = __float2bfloat16(p);
        gPhi[base + i] = h;
        gPlo[base + i] = __float2bfloat16(p - __bfloat162float(h));
    }
}

__global__ __launch_bounds__(256) void k_hmean() {
    int idx = blockIdx.x * 256 + threadIdx.x;
    if (idx >= Bc * Sc * Cc) return;
    int b = idx / (Sc * Cc);
    int rem = idx % (Sc * Cc);
    float s = 0.f;
#pragma unroll
    for (int h = 0; h < Hc; h++)
        s += g_CTXH[((size_t)(b * Hc + h) * Sc * Cc) + rem];
    float v = 0.25f * s;
    bf16 hh = __float2bfloat16(v);
    gCThi[idx] = hh;
    gCTlo[idx] = __float2bfloat16(v - __bfloat162float(hh));
}

// ---------------- launch -------------------------------------------------------
extern "C" void kernel_launch(void* const* d_in, const int* in_sizes, int n_in,
                              void* d_out, int out_size) {
    const float* emb = (const float*)d_in[0];
    const float* Wq  = (const float*)d_in[1];
    const float* Wk  = (const float*)d_in[2];
    const float* Wv  = (const float*)d_in[3];
    const float* Wo  = (const float*)d_in[4];
    float* out = (float*)d_out;

    // input conversions
    k_transpose<<<dim3(7, 8, Bc * Tc), dim3(32, 8)>>>(emb);
    {
        bf16 *h, *l;
        cudaGetSymbolAddress((void**)&h, g_Wqhi); cudaGetSymbolAddress((void**)&l, g_Wqlo);
        k_cvt<<<(Hc * Cc * Cc + 255) / 256, 256>>>(Wq, h, l, Hc * Cc * Cc);
        cudaGetSymbolAddress((void**)&h, g_Wkhi); cudaGetSymbolAddress((void**)&l, g_Wklo);
        k_cvt<<<(Hc * Cc * Cc + 255) / 256, 256>>>(Wk, h, l, Hc * Cc * Cc);
        cudaGetSymbolAddress((void**)&h, g_Wvhi); cudaGetSymbolAddress((void**)&l, g_Wvlo);
        k_cvt<<<(Hc * Cc * Cc + 255) / 256, 256>>>(Wv, h, l, Hc * Cc * Cc);
        cudaGetSymbolAddress((void**)&h, g_Wohi); cudaGetSymbolAddress((void**)&l, g_Wolo);
        k_cvt<<<(Cc * Cc + 255) / 256, 256>>>(Wo, h, l, Cc * Cc);
    }

    // QKV projections (HMMA, bf16 split)
    k_gemm_qkv<<<dim3(13, 2, 3 * BHc), 128>>>();
    // V transpose+convert for ctx GEMM B-operand
    k_vtrans<<<dim3(49, 8, BHc), dim3(32, 8)>>>();
    // scores + fused stage-1 instance-norm stats
    k_gemm_sc<<<dim3(13, 13, BHc), 128>>>();
    k_stats2<<<BHc, 256>>>();
    // norm + softmax -> bf16 hi/lo probs
    k_softmax<<<BHc * Sc, 256>>>();
    // ctx = probs @ V
    k_gemm_ctx<<<dim3(13, 2, BHc), 128>>>();
    // head mean -> bf16 hi/lo
    k_hmean<<<(Bc * Sc * Cc + 255) / 256, 256>>>();
    // output projection into d_out
    k_gemm_o<<<dim3(49, 2, 1), 128>>>(out);
}

// round 4
// speedup vs baseline: 3.4844x; 1.2091x over previous
#include <cuda_runtime.h>
#include <cuda_bf16.h>
#include <cstdint>
#include <math.h>

// ---------------- problem constants ----------------
#define Bc 4
#define Tc 8
#define Cc 256
#define Nc 196
#define Hc 4
#define Sc (Tc * Nc)          // 1568
#define BHc (Bc * Hc)         // 16
#define MSc (Bc * Sc)         // 6272
#define EPSc 1e-5f
#define NTILE (13 * 13)       // score tiles per bh

typedef __nv_bfloat16 bf16;

// ---------------- scratch (device globals) ----------------------------------
__device__ bf16  g_Xhi[Bc * Sc * Cc],  g_Xlo[Bc * Sc * Cc];
__device__ bf16  g_Wqhi[Hc * Cc * Cc], g_Wqlo[Hc * Cc * Cc];
__device__ bf16  g_Wkhi[Hc * Cc * Cc], g_Wklo[Hc * Cc * Cc];
__device__ bf16  g_Wvhi[Hc * Cc * Cc], g_Wvlo[Hc * Cc * Cc];
__device__ bf16  g_Wohi[Cc * Cc],      g_Wolo[Cc * Cc];
__device__ bf16  gQhi[BHc * Sc * Cc],  gQlo[BHc * Sc * Cc];
__device__ bf16  gKhi[BHc * Sc * Cc],  gKlo[BHc * Sc * Cc];
__device__ float g_Vf32[BHc * Sc * Cc];
__device__ bf16  gVThi[BHc * Cc * Sc], gVTlo[BHc * Cc * Sc];
__device__ float g_S[(size_t)BHc * Sc * Sc];            // fp32 scores
__device__ bf16  gPhi[(size_t)BHc * Sc * Sc], gPlo[(size_t)BHc * Sc * Sc];
__device__ float g_CTXH[BHc * Sc * Cc];
__device__ bf16  gCThi[Bc * Sc * Cc],  gCTlo[Bc * Sc * Cc];
__device__ float g_part[BHc * NTILE * 2];
__device__ float g_mean[BHc], g_rstd[BHc];

// ---------------- PTX helpers ------------------------------------------------
__device__ __forceinline__ uint32_t cvta_smem(const void* p) {
    uint32_t a;
    asm("{ .reg .u64 t; cvta.to.shared.u64 t, %1; cvt.u32.u64 %0, t; }" : "=r"(a) : "l"(p));
    return a;
}

__device__ __forceinline__ void ldsm_x4(uint32_t& r0, uint32_t& r1, uint32_t& r2,
                                        uint32_t& r3, uint32_t addr) {
    asm volatile("ldmatrix.sync.aligned.m8n8.x4.shared.b16 {%0,%1,%2,%3}, [%4];"
                 : "=r"(r0), "=r"(r1), "=r"(r2), "=r"(r3) : "r"(addr));
}

__device__ __forceinline__ void mma16816(float* d, const uint32_t* a, const uint32_t* b) {
    asm volatile("mma.sync.aligned.m16n8k16.row.col.f32.bf16.bf16.f32 "
                 "{%0,%1,%2,%3}, {%4,%5,%6,%7}, {%8,%9}, {%0,%1,%2,%3};"
                 : "+f"(d[0]), "+f"(d[1]), "+f"(d[2]), "+f"(d[3])
                 : "r"(a[0]), "r"(a[1]), "r"(a[2]), "r"(a[3]), "r"(b[0]), "r"(b[1]));
}

__device__ __forceinline__ void cp16(uint32_t dst, const void* src, bool v) {
    asm volatile("cp.async.cg.shared.global [%0], [%1], 16, %2;"
                 :: "r"(dst), "l"(src), "r"(v ? 16u : 0u) : "memory");
}

// ---------------- generic 128x128 bf16-split HMMA GEMM (pipelined) -----------
// NT form: C[m,n] = alpha * sum_k A[m,k]*B[n,k]; A,B row-major (k contiguous)
#define EPI_F32    0
#define EPI_SCORES 1
#define EPI_SPLIT  2

#define KCH 32
#define ROWB 80                       // 64B data + 16B pad (conflict-free LDSM)
#define ST_ARR (128 * ROWB)           // 10240 B per operand array per stage
#define ST_BYTES (4 * ST_ARR)         // 40960 B per stage
#define SM_ST 128                     // stage base offset (red lives at 0)
#define SMEM_GEMM (SM_ST + 2 * ST_BYTES)

static __device__ __forceinline__ void gemm_body(
        const bf16* __restrict__ Ahi, const bf16* __restrict__ Alo,
        const bf16* __restrict__ Bhi, const bf16* __restrict__ Blo,
        int M, int N, int K, int lda, int ldb,
        int m0, int n0, int epi, float alpha,
        float* Cf, bf16* Chi, bf16* Clo, int ldc, float* part) {
    extern __shared__ char smem[];
    float* red = (float*)smem;
    const int tid = threadIdx.x;            // 128 threads, 4 warps
    const int wid = tid >> 5, lane = tid & 31;
    const int wm = (wid >> 1) * 64, wn = (wid & 1) * 64;
    const uint32_t sb = cvta_smem(smem);

    float acc[4][8][4];
#pragma unroll
    for (int i = 0; i < 4; i++)
#pragma unroll
        for (int j = 0; j < 8; j++)
#pragma unroll
            for (int e = 0; e < 4; e++) acc[i][j][e] = 0.f;

    const int nch = K / KCH;   // K is a multiple of 32 for all call sites

    // --- cp.async issue of one K32 chunk into stage (ch&1) ---
    #define ISSUE(ch)                                                            \
    do {                                                                         \
        const int k0_ = (ch) * KCH;                                              \
        const uint32_t stb_ = sb + SM_ST + ((ch) & 1) * ST_BYTES;                \
        _Pragma("unroll")                                                        \
        for (int l = 0; l < 16; l++) {                                           \
            int it = tid + l * 128;                                              \
            int arr = it >> 9;                                                   \
            int rem = it & 511;                                                  \
            int r = rem >> 2, u = rem & 3;                                       \
            const bf16* src;                                                     \
            bool valid;                                                          \
            if (arr < 2) {                                                       \
                valid = (m0 + r) < M;                                            \
                size_t ro = valid ? (size_t)(m0 + r) * lda : 0;                  \
                src = (arr == 0 ? Ahi : Alo) + ro + k0_ + u * 8;                 \
            } else {                                                             \
                valid = (n0 + r) < N;                                            \
                size_t ro = valid ? (size_t)(n0 + r) * ldb : 0;                  \
                src = (arr == 2 ? Bhi : Blo) + ro + k0_ + u * 8;                 \
            }                                                                    \
            cp16(stb_ + arr * ST_ARR + r * ROWB + u * 16, src, valid);           \
        }                                                                        \
    } while (0)

    ISSUE(0);
    asm volatile("cp.async.commit_group;" ::: "memory");

    const uint32_t lrow = (uint32_t)(lane & 15);
    const uint32_t lu = (uint32_t)(lane >> 4);

    for (int ch = 0; ch < nch; ch++) {
        if (ch + 1 < nch) ISSUE(ch + 1);
        asm volatile("cp.async.commit_group;" ::: "memory");
        asm volatile("cp.async.wait_group 1;" ::: "memory");
        __syncthreads();

        const uint32_t stb = sb + SM_ST + (ch & 1) * ST_BYTES;
#pragma unroll
        for (int ku = 0; ku < 2; ku++) {
            uint32_t af[2][4][4];
            uint32_t bfr[2][8][2];
#pragma unroll
            for (int hl = 0; hl < 2; hl++) {
#pragma unroll
                for (int im = 0; im < 4; im++) {
                    uint32_t addr = stb + hl * ST_ARR +
                                    (wm + im * 16 + lrow) * ROWB + ku * 32 + lu * 16;
                    ldsm_x4(af[hl][im][0], af[hl][im][1], af[hl][im][2], af[hl][im][3], addr);
                }
#pragma unroll
                for (int inn = 0; inn < 4; inn++) {
                    uint32_t addr = stb + (2 + hl) * ST_ARR +
                                    (wn + inn * 16 + lrow) * ROWB + ku * 32 + lu * 16;
                    uint32_t r0, r1, r2, r3;
                    ldsm_x4(r0, r1, r2, r3, addr);
                    bfr[hl][inn * 2 + 0][0] = r0; bfr[hl][inn * 2 + 0][1] = r2;
                    bfr[hl][inn * 2 + 1][0] = r1; bfr[hl][inn * 2 + 1][1] = r3;
                }
            }
#pragma unroll
            for (int im = 0; im < 4; im++)
#pragma unroll
                for (int jn = 0; jn < 8; jn++) {
                    mma16816(acc[im][jn], af[0][im], bfr[0][jn]);  // hi*hi
                    mma16816(acc[im][jn], af[0][im], bfr[1][jn]);  // hi*lo
                    mma16816(acc[im][jn], af[1][im], bfr[0][jn]);  // lo*hi
                }
        }
        __syncthreads();   // stage (ch&1) reused by ISSUE at iteration ch+1
    }
    #undef ISSUE

    // ---------------- epilogue ----------------
    float psum = 0.f, psq = 0.f;
#pragma unroll
    for (int im = 0; im < 4; im++) {
#pragma unroll
        for (int jn = 0; jn < 8; jn++) {
            int r0 = m0 + wm + im * 16 + (lane >> 2);
            int cn = n0 + wn + jn * 8 + (lane & 3) * 2;
            bool cv = cn < N;
            float v0 = acc[im][jn][0] * alpha, v1 = acc[im][jn][1] * alpha;
            float v2 = acc[im][jn][2] * alpha, v3 = acc[im][jn][3] * alpha;
            if (epi == EPI_SPLIT) {
                if (cv && r0 < M) {
                    bf16 h0 = __float2bfloat16(v0), h1 = __float2bfloat16(v1);
                    __nv_bfloat162 hh; hh.x = h0; hh.y = h1;
                    __nv_bfloat162 ll;
                    ll.x = __float2bfloat16(v0 - __bfloat162float(h0));
                    ll.y = __float2bfloat16(v1 - __bfloat162float(h1));
                    *(__nv_bfloat162*)&Chi[(size_t)r0 * ldc + cn] = hh;
                    *(__nv_bfloat162*)&Clo[(size_t)r0 * ldc + cn] = ll;
                }
                if (cv && r0 + 8 < M) {
                    bf16 h2 = __float2bfloat16(v2), h3 = __float2bfloat16(v3);
                    __nv_bfloat162 hh; hh.x = h2; hh.y = h3;
                    __nv_bfloat162 ll;
                    ll.x = __float2bfloat16(v2 - __bfloat162float(h2));
                    ll.y = __float2bfloat16(v3 - __bfloat162float(h3));
                    *(__nv_bfloat162*)&Chi[(size_t)(r0 + 8) * ldc + cn] = hh;
                    *(__nv_bfloat162*)&Clo[(size_t)(r0 + 8) * ldc + cn] = ll;
                }
            } else {
                if (cv && r0 < M) {
                    *(float2*)&Cf[(size_t)r0 * ldc + cn] = make_float2(v0, v1);
                    psum += v0 + v1; psq += v0 * v0 + v1 * v1;
                }
                if (cv && r0 + 8 < M) {
                    *(float2*)&Cf[(size_t)(r0 + 8) * ldc + cn] = make_float2(v2, v3);
                    psum += v2 + v3; psq += v2 * v2 + v3 * v3;
                }
            }
        }
    }
    if (epi == EPI_SCORES) {
#pragma unroll
        for (int o = 16; o; o >>= 1) {
            psum += __shfl_xor_sync(0xffffffffu, psum, o);
            psq  += __shfl_xor_sync(0xffffffffu, psq,  o);
        }
        if (lane == 0) { red[wid] = psum; red[4 + wid] = psq; }
        __syncthreads();
        if (tid == 0) {
            part[0] = red[0] + red[1] + red[2] + red[3];
            part[1] = red[4] + red[5] + red[6] + red[7];
        }
    }
}

// ---------------- GEMM wrappers ----------------------------------------------
__global__ __launch_bounds__(128) void k_gemm_qkv() {
    int z = blockIdx.z;
    int bh = z / 3, which = z % 3;
    int b = bh / Hc, h = bh % Hc;
    const bf16* Ah = g_Xhi + (size_t)b * Sc * Cc;
    const bf16* Al = g_Xlo + (size_t)b * Sc * Cc;
    const bf16 *Bh, *Bl;
    if (which == 0)      { Bh = g_Wqhi + (size_t)h * Cc * Cc; Bl = g_Wqlo + (size_t)h * Cc * Cc; }
    else if (which == 1) { Bh = g_Wkhi + (size_t)h * Cc * Cc; Bl = g_Wklo + (size_t)h * Cc * Cc; }
    else                 { Bh = g_Wvhi + (size_t)h * Cc * Cc; Bl = g_Wvlo + (size_t)h * Cc * Cc; }
    int m0 = blockIdx.x * 128, n0 = blockIdx.y * 128;
    if (which == 2) {
        gemm_body(Ah, Al, Bh, Bl, Sc, Cc, Cc, Cc, Cc, m0, n0, EPI_F32, 1.f,
                  g_Vf32 + (size_t)bh * Sc * Cc, nullptr, nullptr, Cc, nullptr);
    } else {
        bf16* Chi = (which == 0 ? gQhi : gKhi) + (size_t)bh * Sc * Cc;
        bf16* Clo = (which == 0 ? gQlo : gKlo) + (size_t)bh * Sc * Cc;
        gemm_body(Ah, Al, Bh, Bl, Sc, Cc, Cc, Cc, Cc, m0, n0, EPI_SPLIT, 1.f,
                  nullptr, Chi, Clo, Cc, nullptr);
    }
}

__global__ __launch_bounds__(128) void k_gemm_sc() {
    int bh = blockIdx.z;
    int m0 = blockIdx.x * 128, n0 = blockIdx.y * 128;
    float alpha = rsqrtf((float)Sc);
    gemm_body(gQhi + (size_t)bh * Sc * Cc, gQlo + (size_t)bh * Sc * Cc,
              gKhi + (size_t)bh * Sc * Cc, gKlo + (size_t)bh * Sc * Cc,
              Sc, Sc, Cc, Cc, Cc, m0, n0, EPI_SCORES, alpha,
              g_S + (size_t)bh * Sc * Sc, nullptr, nullptr, Sc,
              &g_part[((size_t)bh * NTILE + blockIdx.y * 13 + blockIdx.x) * 2]);
}

__global__ __launch_bounds__(128) void k_gemm_ctx() {
    int bh = blockIdx.z;
    int m0 = blockIdx.x * 128, n0 = blockIdx.y * 128;
    gemm_body(gPhi + (size_t)bh * Sc * Sc, gPlo + (size_t)bh * Sc * Sc,
              gVThi + (size_t)bh * Cc * Sc, gVTlo + (size_t)bh * Cc * Sc,
              Sc, Cc, Sc, Sc, Sc, m0, n0, EPI_F32, 1.f,
              g_CTXH + (size_t)bh * Sc * Cc, nullptr, nullptr, Cc, nullptr);
}

__global__ __launch_bounds__(128) void k_gemm_o(float* __restrict__ out) {
    int m0 = blockIdx.x * 128, n0 = blockIdx.y * 128;
    gemm_body(gCThi, gCTlo, g_Wohi, g_Wolo,
              MSc, Cc, Cc, Cc, Cc, m0, n0, EPI_F32, 1.f,
              out, nullptr, nullptr, Cc, nullptr);
}

// ---------------- elementwise / reshape kernels -------------------------------
__global__ void k_transpose(const float* __restrict__ emb) {
    __shared__ float tile[32][33];
    int bt = blockIdx.z;
    int n0 = blockIdx.x * 32, c0 = blockIdx.y * 32;
    int x = threadIdx.x, y = threadIdx.y;
    const float* src = emb + (size_t)bt * Cc * Nc;
    bf16* dh = g_Xhi + (size_t)bt * Nc * Cc;
    bf16* dl = g_Xlo + (size_t)bt * Nc * Cc;
#pragma unroll
    for (int i = 0; i < 32; i += 8) {
        int c = c0 + y + i, n = n0 + x;
        tile[y + i][x] = (n < Nc) ? src[c * Nc + n] : 0.f;
    }
    __syncthreads();
#pragma unroll
    for (int i = 0; i < 32; i += 8) {
        int n = n0 + y + i, c = c0 + x;
        if (n < Nc) {
            float v = tile[x][y + i];
            bf16 h = __float2bfloat16(v);
            dh[n * Cc + c] = h;
            dl[n * Cc + c] = __float2bfloat16(v - __bfloat162float(h));
        }
    }
}

__global__ void k_cvt(const float* __restrict__ s, bf16* __restrict__ h,
                      bf16* __restrict__ l, int n) {
    int i = blockIdx.x * 256 + threadIdx.x;
    if (i < n) {
        float v = s[i];
        bf16 x = __float2bfloat16(v);
        h[i] = x;
        l[i] = __float2bfloat16(v - __bfloat162float(x));
    }
}

// V [bh][S][C] fp32 -> VT [bh][C][S] bf16 hi/lo
__global__ void k_vtrans() {
    __shared__ float t[32][33];
    int bh = blockIdx.z;
    int s0 = blockIdx.x * 32, c0 = blockIdx.y * 32;
    int x = threadIdx.x, y = threadIdx.y;
    const float* V = g_Vf32 + (size_t)bh * Sc * Cc;
    bf16* th = gVThi + (size_t)bh * Cc * Sc;
    bf16* tl = gVTlo + (size_t)bh * Cc * Sc;
#pragma unroll
    for (int i = 0; i < 32; i += 8)
        t[y + i][x] = V[(size_t)(s0 + y + i) * Cc + c0 + x];
    __syncthreads();
#pragma unroll
    for (int i = 0; i < 32; i += 8) {
        float v = t[x][y + i];
        bf16 h = __float2bfloat16(v);
        th[(size_t)(c0 + y + i) * Sc + s0 + x] = h;
        tl[(size_t)(c0 + y + i) * Sc + s0 + x] = __float2bfloat16(v - __bfloat162float(h));
    }
}

__global__ __launch_bounds__(256) void k_stats2() {
    int bh = blockIdx.x;
    float s = 0.f, q = 0.f;
    for (int i = threadIdx.x; i < NTILE; i += 256) {
        s += g_part[((size_t)bh * NTILE + i) * 2 + 0];
        q += g_part[((size_t)bh * NTILE + i) * 2 + 1];
    }
    __shared__ float ss[256], sq[256];
    int tid = threadIdx.x;
    ss[tid] = s; sq[tid] = q;
    __syncthreads();
    for (int st = 128; st > 0; st >>= 1) {
        if (tid < st) { ss[tid] += ss[tid + st]; sq[tid] += sq[tid + st]; }
        __syncthreads();
    }
    if (tid == 0) {
        float cnt = (float)Sc * (float)Sc;
        float mean = ss[0] / cnt;
        float var = sq[0] / cnt - mean * mean;
        g_mean[bh] = mean;
        g_rstd[bh] = rsqrtf(var + EPSc);
    }
}

__global__ __launch_bounds__(256) void k_softmax() {
    int row = blockIdx.x;
    int bh = row / Sc;
    size_t base = (size_t)row * Sc;
    __shared__ float buf[Sc];
    __shared__ float red[256];
    int tid = threadIdx.x;
    float mean = g_mean[bh], rstd = g_rstd[bh];

    float lmax = -3.4e38f;
    for (int i = tid; i < Sc; i += 256) {
        float v = (g_S[base + i] - mean) * rstd;
        buf[i] = v;
        lmax = fmaxf(lmax, v);
    }
    red[tid] = lmax;
    __syncthreads();
    for (int st = 128; st > 0; st >>= 1) {
        if (tid < st) red[tid] = fmaxf(red[tid], red[tid + st]);
        __syncthreads();
    }
    float rmax = red[0];
    __syncthreads();

    float lsum = 0.f;
    for (int i = tid; i < Sc; i += 256) {
        float e = __expf(buf[i] - rmax);
        buf[i] = e;
        lsum += e;
    }
    red[tid] = lsum;
    __syncthreads();
    for (int st = 128; st > 0; st >>= 1) {
        if (tid < st) red[tid] += red[tid + st];
        __syncthreads();
    }
    float inv = 1.f / red[0];
    __syncthreads();

    for (int i = tid; i < Sc; i += 256) {
        float p = buf[i] * inv;
        bf16 h = __float2bfloat16(p);
        gPhi[base + i] = h;
        gPlo[base + i] = __float2bfloat16(p - __bfloat162float(h));
    }
}

__global__ __launch_bounds__(256) void k_hmean() {
    int idx = blockIdx.x * 256 + threadIdx.x;
    if (idx >= Bc * Sc * Cc) return;
    int b = idx / (Sc * Cc);
    int rem = idx % (Sc * Cc);
    float s = 0.f;
#pragma unroll
    for (int h = 0; h < Hc; h++)
        s += g_CTXH[((size_t)(b * Hc + h) * Sc * Cc) + rem];
    float v = 0.25f * s;
    bf16 hh = __float2bfloat16(v);
    gCThi[idx] = hh;
    gCTlo[idx] = __float2bfloat16(v - __bfloat162float(hh));
}

// ---------------- launch -------------------------------------------------------
extern "C" void kernel_launch(void* const* d_in, const int* in_sizes, int n_in,
                              void* d_out, int out_size) {
    const float* emb = (const float*)d_in[0];
    const float* Wq  = (const float*)d_in[1];
    const float* Wk  = (const float*)d_in[2];
    const float* Wv  = (const float*)d_in[3];
    const float* Wo  = (const float*)d_in[4];
    float* out = (float*)d_out;

    static bool attr_done = false;
    if (!attr_done) {
        cudaFuncSetAttribute(k_gemm_qkv, cudaFuncAttributeMaxDynamicSharedMemorySize, SMEM_GEMM);
        cudaFuncSetAttribute(k_gemm_sc,  cudaFuncAttributeMaxDynamicSharedMemorySize, SMEM_GEMM);
        cudaFuncSetAttribute(k_gemm_ctx, cudaFuncAttributeMaxDynamicSharedMemorySize, SMEM_GEMM);
        cudaFuncSetAttribute(k_gemm_o,   cudaFuncAttributeMaxDynamicSharedMemorySize, SMEM_GEMM);
        attr_done = true;
    }

    // input conversions
    k_transpose<<<dim3(7, 8, Bc * Tc), dim3(32, 8)>>>(emb);
    {
        bf16 *h, *l;
        cudaGetSymbolAddress((void**)&h, g_Wqhi); cudaGetSymbolAddress((void**)&l, g_Wqlo);
        k_cvt<<<(Hc * Cc * Cc + 255) / 256, 256>>>(Wq, h, l, Hc * Cc * Cc);
        cudaGetSymbolAddress((void**)&h, g_Wkhi); cudaGetSymbolAddress((void**)&l, g_Wklo);
        k_cvt<<<(Hc * Cc * Cc + 255) / 256, 256>>>(Wk, h, l, Hc * Cc * Cc);
        cudaGetSymbolAddress((void**)&h, g_Wvhi); cudaGetSymbolAddress((void**)&l, g_Wvlo);
        k_cvt<<<(Hc * Cc * Cc + 255) / 256, 256>>>(Wv, h, l, Hc * Cc * Cc);
        cudaGetSymbolAddress((void**)&h, g_Wohi); cudaGetSymbolAddress((void**)&l, g_Wolo);
        k_cvt<<<(Cc * Cc + 255) / 256, 256>>>(Wo, h, l, Cc * Cc);
    }

    // QKV projections (HMMA, bf16 split, pipelined)
    k_gemm_qkv<<<dim3(13, 2, 3 * BHc), 128, SMEM_GEMM>>>();
    // V transpose+convert for ctx GEMM B-operand
    k_vtrans<<<dim3(49, 8, BHc), dim3(32, 8)>>>();
    // scores + fused stage-1 instance-norm stats
    k_gemm_sc<<<dim3(13, 13, BHc), 128, SMEM_GEMM>>>();
    k_stats2<<<BHc, 256>>>();
    // norm + softmax -> bf16 hi/lo probs
    k_softmax<<<BHc * Sc, 256>>>();
    // ctx = probs @ V
    k_gemm_ctx<<<dim3(13, 2, BHc), 128, SMEM_GEMM>>>();
    // head mean -> bf16 hi/lo
    k_hmean<<<(Bc * Sc * Cc + 255) / 256, 256>>>();
    // output projection into d_out
    k_gemm_o<<<dim3(49, 2, 1), 128, SMEM_GEMM>>>(out);
}